// round 4
// baseline (speedup 1.0000x reference)
#include <cuda_runtime.h>
#include <cuda_bf16.h>
#include <math.h>

#define M_TOK   16384
#define DIMK    7168
#define NEXP    256
#define NGROUP  8
#define TOPKG   4
#define TOPK    8
#define RSCALE  2.5f
#define TAU     4e-6f

__device__ float g_scores[(size_t)M_TOK * NEXP];
__device__ int   g_risk_count;
__device__ int   g_risk_ids[M_TOK];

// ---------------------------------------------------------------------------
// Pass-A GEMM: C[M,N] = A[M,K]*B[N,K]^T, fp32, serial ascending-k accumulator.
// BM=128, BN=64, BK=16, 256 threads, 8x4 microtile, double-buffered smem.
// ---------------------------------------------------------------------------
#define BM 128
#define BN 64
#define BK 16
#define NT (DIMK / BK)

__global__ __launch_bounds__(256, 2) void gate_gemm_kernel(
    const float* __restrict__ A, const float* __restrict__ B)
{
    __shared__ float As[2][BK][BM];
    __shared__ float Bs[2][BK][BN];

    const int tid = threadIdx.x;
    const int tx  = tid & 15;
    const int ty  = tid >> 4;
    const int m0  = blockIdx.y * BM;
    const int n0  = blockIdx.x * BN;

    float acc[8][4];
#pragma unroll
    for (int i = 0; i < 8; i++)
#pragma unroll
        for (int j = 0; j < 4; j++) acc[i][j] = 0.0f;

    const int arow = tid >> 2;
    const int ac4  = (tid & 3) << 2;
    const float* Ap0 = A + (size_t)(m0 + arow)      * DIMK + ac4;
    const float* Ap1 = A + (size_t)(m0 + arow + 64) * DIMK + ac4;
    const float* Bp  = B + (size_t)(n0 + arow)      * DIMK + ac4;

    {
        float4 va0 = *reinterpret_cast<const float4*>(Ap0);
        float4 va1 = *reinterpret_cast<const float4*>(Ap1);
        float4 vb  = *reinterpret_cast<const float4*>(Bp);
        As[0][ac4 + 0][arow] = va0.x; As[0][ac4 + 1][arow] = va0.y;
        As[0][ac4 + 2][arow] = va0.z; As[0][ac4 + 3][arow] = va0.w;
        As[0][ac4 + 0][arow + 64] = va1.x; As[0][ac4 + 1][arow + 64] = va1.y;
        As[0][ac4 + 2][arow + 64] = va1.z; As[0][ac4 + 3][arow + 64] = va1.w;
        Bs[0][ac4 + 0][arow] = vb.x; Bs[0][ac4 + 1][arow] = vb.y;
        Bs[0][ac4 + 2][arow] = vb.z; Bs[0][ac4 + 3][arow] = vb.w;
    }
    __syncthreads();

    for (int kt = 0; kt < NT; kt++) {
        const int cur = kt & 1;
        float4 na0, na1, nb;
        if (kt + 1 < NT) {
            int off = (kt + 1) * BK;
            na0 = *reinterpret_cast<const float4*>(Ap0 + off);
            na1 = *reinterpret_cast<const float4*>(Ap1 + off);
            nb  = *reinterpret_cast<const float4*>(Bp  + off);
        }

#pragma unroll
        for (int kk = 0; kk < BK; kk++) {
            float a[8], b[4];
            *reinterpret_cast<float4*>(&a[0]) = *reinterpret_cast<const float4*>(&As[cur][kk][ty * 4]);
            *reinterpret_cast<float4*>(&a[4]) = *reinterpret_cast<const float4*>(&As[cur][kk][ty * 4 + 64]);
            *reinterpret_cast<float4*>(&b[0]) = *reinterpret_cast<const float4*>(&Bs[cur][kk][tx * 4]);
#pragma unroll
            for (int i = 0; i < 8; i++)
#pragma unroll
                for (int j = 0; j < 4; j++)
                    acc[i][j] = fmaf(a[i], b[j], acc[i][j]);
        }

        if (kt + 1 < NT) {
            const int nxt = cur ^ 1;
            As[nxt][ac4 + 0][arow] = na0.x; As[nxt][ac4 + 1][arow] = na0.y;
            As[nxt][ac4 + 2][arow] = na0.z; As[nxt][ac4 + 3][arow] = na0.w;
            As[nxt][ac4 + 0][arow + 64] = na1.x; As[nxt][ac4 + 1][arow + 64] = na1.y;
            As[nxt][ac4 + 2][arow + 64] = na1.z; As[nxt][ac4 + 3][arow + 64] = na1.w;
            Bs[nxt][ac4 + 0][arow] = nb.x; Bs[nxt][ac4 + 1][arow] = nb.y;
            Bs[nxt][ac4 + 2][arow] = nb.z; Bs[nxt][ac4 + 3][arow] = nb.w;
        }
        __syncthreads();
    }

#pragma unroll
    for (int i = 0; i < 8; i++) {
        int r = m0 + ((i < 4) ? (ty * 4 + i) : (64 + ty * 4 + (i - 4)));
        float4 v = make_float4(acc[i][0], acc[i][1], acc[i][2], acc[i][3]);
        *reinterpret_cast<float4*>(&g_scores[(size_t)r * NEXP + n0 + tx * 4]) = v;
    }
}

// ---------------------------------------------------------------------------
__device__ __forceinline__ unsigned float_ord(float f) {
    unsigned u = __float_as_uint(f);
    return (u & 0x80000000u) ? ~u : (u | 0x80000000u);
}
__device__ __forceinline__ float ord_to_float(unsigned o) {
    unsigned u = (o & 0x80000000u) ? (o ^ 0x80000000u) : ~o;
    return __uint_as_float(u);
}

// Shared routing core: one 256-thread block handles one token.
// detect_risk: pass A flags near-tie tokens into g_risk_ids.
__device__ __forceinline__ void route_token(float sb, int t, int e,
                                            float* out_w, float* out_i,
                                            bool detect_risk)
{
    const int warp = e >> 5, lane = e & 31;

    __shared__ float sbs[NEXP];
    __shared__ unsigned long long keys[NEXP];
    __shared__ float gsc[NGROUP];
    __shared__ int   gsel[NGROUP];
    __shared__ unsigned long long warpmax[NGROUP];
    __shared__ int   sel[TOPK + 1];
    __shared__ float selv[TOPK + 1];
    __shared__ int   s_risky;

    if (e == 0) s_risky = 0;
    sbs[e] = sb;

    // per-group top-3 (top-2 sum for gsc; v2-v3 gap guards membership)
    float m1 = sb;
#pragma unroll
    for (int o = 16; o; o >>= 1) m1 = fmaxf(m1, __shfl_xor_sync(0xffffffffu, m1, o));
    unsigned bal1 = __ballot_sync(0xffffffffu, sb == m1);
    int arg1 = __ffs(bal1) - 1;
    float x2 = (lane == arg1) ? -INFINITY : sb;
    float v2 = x2;
#pragma unroll
    for (int o = 16; o; o >>= 1) v2 = fmaxf(v2, __shfl_xor_sync(0xffffffffu, v2, o));
    unsigned bal2 = __ballot_sync(0xffffffffu, x2 == v2);
    int arg2 = __ffs(bal2) - 1;
    float x3 = (lane == arg1 || lane == arg2) ? -INFINITY : sb;
    float v3 = x3;
#pragma unroll
    for (int o = 16; o; o >>= 1) v3 = fmaxf(v3, __shfl_xor_sync(0xffffffffu, v3, o));
    if (lane == 0) {
        gsc[warp] = __fadd_rn(m1, v2);
        if (detect_risk && (v2 - v3) < TAU) s_risky = 1;
    }
    __syncthreads();

    // top-4 groups; 5 rounds to get the 4th/5th gap
    if (e == 0) {
        float bvals[TOPKG + 1];
#pragma unroll
        for (int g = 0; g < NGROUP; g++) gsel[g] = 0;
#pragma unroll
        for (int r = 0; r < TOPKG + 1; r++) {
            int bi = -1; float bv = -INFINITY;
#pragma unroll
            for (int g = 0; g < NGROUP; g++)
                if (!gsel[g] && gsc[g] > bv) { bv = gsc[g]; bi = g; }
            bvals[r] = bv;
            if (r < TOPKG) gsel[bi] = 1;
        }
        if (detect_risk && (bvals[TOPKG - 1] - bvals[TOPKG]) < TAU) s_risky = 1;
    }
    __syncthreads();

    // masked vector: unselected groups -> 0.0 (reference semantics)
    float mv = gsel[warp] ? sb : 0.0f;
    keys[e] = ((unsigned long long)float_ord(mv) << 32) | (unsigned)(255 - e);
    __syncthreads();

    // top-9 (8 outputs + one extra for the boundary gap), stable tie-break
#pragma unroll
    for (int r = 0; r < TOPK + 1; r++) {
        unsigned long long k = keys[e];
#pragma unroll
        for (int o = 16; o; o >>= 1) {
            unsigned long long k2 = __shfl_xor_sync(0xffffffffu, k, o);
            k = (k2 > k) ? k2 : k;
        }
        if (lane == 0) warpmax[warp] = k;
        __syncthreads();
        if (e == 0) {
            unsigned long long best = warpmax[0];
#pragma unroll
            for (int w = 1; w < NGROUP; w++) if (warpmax[w] > best) best = warpmax[w];
            int win = 255 - (int)(best & 0xFFu);
            sel[r]  = win;
            selv[r] = ord_to_float((unsigned)(best >> 32));
            keys[win] = 0ull;
        }
        __syncthreads();
    }

    if (e == 0) {
        if (detect_risk) {
#pragma unroll
            for (int r = 0; r < TOPK; r++)
                if ((selv[r] - selv[r + 1]) < TAU) s_risky = 1;
            if (s_risky) {
                int id = atomicAdd(&g_risk_count, 1);
                g_risk_ids[id] = t;
            }
        }
        float sum = 0.0f;
#pragma unroll
        for (int j = 0; j < TOPK; j++) sum = __fadd_rn(sum, sbs[sel[j]]);
#pragma unroll
        for (int j = 0; j < TOPK; j++) {
            out_w[(size_t)t * TOPK + j] = __fmul_rn(__fdiv_rn(sbs[sel[j]], sum), RSCALE);
            out_i[(size_t)t * TOPK + j] = (float)sel[j];
        }
    }
}

__global__ void gate_zero_kernel() { g_risk_count = 0; }

__global__ __launch_bounds__(256) void gate_routeA_kernel(
    const float* __restrict__ bias, float* __restrict__ out_w, float* __restrict__ out_i)
{
    const int t = blockIdx.x;
    const int e = threadIdx.x;
    float s = g_scores[(size_t)t * NEXP + e];
    // two-step rounding as reference: fp32(sigmoid) then fp32 add bias
    float sg = (float)(1.0 / (1.0 + exp(-(double)s)));
    float sb = __fadd_rn(sg, bias[e]);
    route_token(sb, t, e, out_w, out_i, true);
}

// Pass B: exact fp64 rescoring of flagged tokens, then identical routing.
__global__ __launch_bounds__(256) void gate_routeB_kernel(
    const float* __restrict__ A, const float* __restrict__ B,
    const float* __restrict__ bias, float* __restrict__ out_w, float* __restrict__ out_i)
{
    const int cnt = g_risk_count;
    const int e = threadIdx.x;
    for (int i = blockIdx.x; i < cnt; i += gridDim.x) {
        const int t = g_risk_ids[i];
        const float4* a4 = reinterpret_cast<const float4*>(A + (size_t)t * DIMK);
        const float4* b4 = reinterpret_cast<const float4*>(B + (size_t)e * DIMK);
        double acc = 0.0;
        for (int k = 0; k < DIMK / 4; k++) {
            float4 av = a4[k], bv = b4[k];
            acc = fma((double)av.x, (double)bv.x, acc);
            acc = fma((double)av.y, (double)bv.y, acc);
            acc = fma((double)av.z, (double)bv.z, acc);
            acc = fma((double)av.w, (double)bv.w, acc);
        }
        double sg64 = 1.0 / (1.0 + exp(-acc));
        float sg = (float)sg64;                       // fp32(sigmoid_true)
        float sb = __fadd_rn(sg, bias[e]);            // then fp32 + bias
        __syncthreads();
        route_token(sb, t, e, out_w, out_i, false);
        __syncthreads();
    }
}

// ---------------------------------------------------------------------------
extern "C" void kernel_launch(void* const* d_in, const int* in_sizes, int n_in,
                              void* d_out, int out_size)
{
    const float* x = (const float*)d_in[0];
    const float* w = (const float*)d_in[1];
    const float* b = (const float*)d_in[2];
    float* out = (float*)d_out;
    float* out_w = out;
    float* out_i = out + (size_t)out_size / 2;

    gate_zero_kernel<<<1, 1>>>();
    dim3 grid(NEXP / BN, M_TOK / BM);
    gate_gemm_kernel<<<grid, 256>>>(x, w);
    gate_routeA_kernel<<<M_TOK, 256>>>(b, out_w, out_i);
    gate_routeB_kernel<<<512, 256>>>(x, w, b, out_w, out_i);
}

// round 7
// speedup vs baseline: 2.2538x; 2.2538x over previous
#include <cuda_runtime.h>
#include <cuda_bf16.h>
#include <math.h>
#include <stdint.h>

#define M_TOK   16384
#define DIMK    7168
#define NEXP    256
#define NGROUP  8
#define TOPKG   4
#define TOPK    8
#define RSCALE  2.5f
#define TAU     8e-6f

__device__ float g_scores[(size_t)M_TOK * NEXP];
__device__ float g_wh[(size_t)NEXP * DIMK];
__device__ float g_wm[(size_t)NEXP * DIMK];
__device__ int   g_risk_count;
__device__ int   g_risk_ids[M_TOK];

// ===================== helpers =====================
__device__ __forceinline__ uint32_t smem_u32(const void* p) {
    uint32_t a;
    asm("{ .reg .u64 t; cvta.to.shared.u64 t, %1; cvt.u32.u64 %0, t; }" : "=r"(a) : "l"(p));
    return a;
}
__device__ __forceinline__ void cp_async16(uint32_t dst, const void* src) {
    asm volatile("cp.async.cg.shared.global [%0], [%1], 16;" :: "r"(dst), "l"(src) : "memory");
}
__device__ __forceinline__ void cp_commit() {
    asm volatile("cp.async.commit_group;" ::: "memory");
}
template <int N> __device__ __forceinline__ void cp_wait() {
    asm volatile("cp.async.wait_group %0;" :: "n"(N) : "memory");
}
__device__ __forceinline__ void mma_tf32(float* c, const uint32_t* a, const uint32_t* b) {
    asm volatile(
        "mma.sync.aligned.m16n8k8.row.col.f32.tf32.tf32.f32 "
        "{%0,%1,%2,%3}, {%4,%5,%6,%7}, {%8,%9}, {%0,%1,%2,%3};"
        : "+f"(c[0]), "+f"(c[1]), "+f"(c[2]), "+f"(c[3])
        : "r"(a[0]), "r"(a[1]), "r"(a[2]), "r"(a[3]), "r"(b[0]), "r"(b[1]));
}

#define TF32_MASK 0xFFFFE000u

__global__ __launch_bounds__(512) void presplit_kernel(const float* __restrict__ W) {
    int i = blockIdx.x * 512 + threadIdx.x;
    if (i >= NEXP * DIMK) return;
    float w = W[i];
    float fh = __uint_as_float(__float_as_uint(w) & TF32_MASK);
    g_wh[i] = fh;
    g_wm[i] = w - fh;
}

// ===================== tf32 tensor GEMM, split accumulators =====================
#define BM 128
#define BN 128
#define BK 32
#define KT (DIMK / BK)
#define ROWP 36
#define BUF_FLOATS (3 * BM * ROWP)

__global__ __launch_bounds__(256, 1) void gemm_tc_kernel(const float* __restrict__ X) {
    extern __shared__ float smf[];
    const int tid  = threadIdx.x;
    const int lane = tid & 31;
    const int wid  = tid >> 5;
    const int m0   = blockIdx.y * BM;
    const int n0   = blockIdx.x * BN;
    const int wm_  = (wid >> 1) * 32;
    const int wn_  = (wid & 1) * 64;

    const int lrow = tid >> 3;
    const int lc4  = (tid & 7) << 2;

    float accH[2][8][4], accS[2][8][4];
#pragma unroll
    for (int mi = 0; mi < 2; mi++)
#pragma unroll
        for (int ni = 0; ni < 8; ni++)
#pragma unroll
            for (int q = 0; q < 4; q++) { accH[mi][ni][q] = 0.0f; accS[mi][ni][q] = 0.0f; }

    auto load_tiles = [&](int t, int buf) {
        float* bufp = smf + buf * BUF_FLOATS;
        const int k0 = t * BK;
#pragma unroll
        for (int j = 0; j < 4; j++) {
            int row = lrow + j * 32;
            uint32_t d = smem_u32(bufp + row * ROWP + lc4);
            cp_async16(d, X + (size_t)(m0 + row) * DIMK + k0 + lc4);
            cp_async16(d + BM * ROWP * 4, g_wh + (size_t)(n0 + row) * DIMK + k0 + lc4);
            cp_async16(d + 2 * BM * ROWP * 4, g_wm + (size_t)(n0 + row) * DIMK + k0 + lc4);
        }
    };

    load_tiles(0, 0);
    cp_commit();

    for (int t = 0; t < KT; t++) {
        const int buf = t & 1;
        if (t + 1 < KT) {
            load_tiles(t + 1, buf ^ 1);
            cp_commit();
            cp_wait<1>();
        } else {
            cp_wait<0>();
        }
        __syncthreads();

        const float* As = smf + buf * BUF_FLOATS;
        const float* Bh = As + BM * ROWP;
        const float* Bm = Bh + BM * ROWP;

#pragma unroll
        for (int ks = 0; ks < 4; ks++) {
            const int kk = ks * 8 + (lane & 3);
            uint32_t ah[2][4], am[2][4];
#pragma unroll
            for (int mi = 0; mi < 2; mi++) {
                int r = wm_ + mi * 16 + (lane >> 2);
                float x0 = As[r * ROWP + kk];
                float x1 = As[(r + 8) * ROWP + kk];
                float x2 = As[r * ROWP + kk + 4];
                float x3 = As[(r + 8) * ROWP + kk + 4];
                uint32_t h0 = __float_as_uint(x0) & TF32_MASK;
                uint32_t h1 = __float_as_uint(x1) & TF32_MASK;
                uint32_t h2 = __float_as_uint(x2) & TF32_MASK;
                uint32_t h3 = __float_as_uint(x3) & TF32_MASK;
                ah[mi][0] = h0; ah[mi][1] = h1; ah[mi][2] = h2; ah[mi][3] = h3;
                am[mi][0] = __float_as_uint(x0 - __uint_as_float(h0));
                am[mi][1] = __float_as_uint(x1 - __uint_as_float(h1));
                am[mi][2] = __float_as_uint(x2 - __uint_as_float(h2));
                am[mi][3] = __float_as_uint(x3 - __uint_as_float(h3));
            }
            uint32_t bh[8][2], bm[8][2];
#pragma unroll
            for (int ni = 0; ni < 8; ni++) {
                int n = wn_ + ni * 8 + (lane >> 2);
                bh[ni][0] = __float_as_uint(Bh[n * ROWP + kk]);
                bh[ni][1] = __float_as_uint(Bh[n * ROWP + kk + 4]);
                bm[ni][0] = __float_as_uint(Bm[n * ROWP + kk]);
                bm[ni][1] = __float_as_uint(Bm[n * ROWP + kk + 4]);
            }
#pragma unroll
            for (int mi = 0; mi < 2; mi++)
#pragma unroll
                for (int ni = 0; ni < 8; ni++) {
                    mma_tf32(accH[mi][ni], ah[mi], bh[ni]);   // hi*hi  (large chain)
                    mma_tf32(accS[mi][ni], ah[mi], bm[ni]);   // hi*mid (small chain)
                    mma_tf32(accS[mi][ni], am[mi], bh[ni]);   // mid*hi (small chain)
                }
        }
        __syncthreads();
    }

#pragma unroll
    for (int mi = 0; mi < 2; mi++)
#pragma unroll
        for (int ni = 0; ni < 8; ni++) {
            int row = m0 + wm_ + mi * 16 + (lane >> 2);
            int col = n0 + wn_ + ni * 8 + (lane & 3) * 2;
            *reinterpret_cast<float2*>(&g_scores[(size_t)row * NEXP + col]) =
                make_float2(accH[mi][ni][0] + accS[mi][ni][0], accH[mi][ni][1] + accS[mi][ni][1]);
            *reinterpret_cast<float2*>(&g_scores[(size_t)(row + 8) * NEXP + col]) =
                make_float2(accH[mi][ni][2] + accS[mi][ni][2], accH[mi][ni][3] + accS[mi][ni][3]);
        }
}

// ===================== routing (two-pass) =====================
__device__ __forceinline__ unsigned float_ord(float f) {
    unsigned u = __float_as_uint(f);
    return (u & 0x80000000u) ? ~u : (u | 0x80000000u);
}
__device__ __forceinline__ float ord_to_float(unsigned o) {
    unsigned u = (o & 0x80000000u) ? (o ^ 0x80000000u) : ~o;
    return __uint_as_float(u);
}

__device__ __forceinline__ void route_token(float sb, int t, int e,
                                            float* out_w, float* out_i, bool detect_risk)
{
    const int warp = e >> 5, lane = e & 31;
    __shared__ float sbs[NEXP];
    __shared__ unsigned long long keys[NEXP];
    __shared__ float gsc[NGROUP];
    __shared__ int   gsel[NGROUP];
    __shared__ unsigned long long warpmax[NGROUP];
    __shared__ int   sel[TOPK + 1];
    __shared__ float selv[TOPK + 1];
    __shared__ int   s_risky;

    if (e == 0) s_risky = 0;
    sbs[e] = sb;

    float m1 = sb;
#pragma unroll
    for (int o = 16; o; o >>= 1) m1 = fmaxf(m1, __shfl_xor_sync(0xffffffffu, m1, o));
    unsigned bal1 = __ballot_sync(0xffffffffu, sb == m1);
    int arg1 = __ffs(bal1) - 1;
    float x2 = (lane == arg1) ? -INFINITY : sb;
    float v2 = x2;
#pragma unroll
    for (int o = 16; o; o >>= 1) v2 = fmaxf(v2, __shfl_xor_sync(0xffffffffu, v2, o));
    unsigned bal2 = __ballot_sync(0xffffffffu, x2 == v2);
    int arg2 = __ffs(bal2) - 1;
    float x3 = (lane == arg1 || lane == arg2) ? -INFINITY : sb;
    float v3 = x3;
#pragma unroll
    for (int o = 16; o; o >>= 1) v3 = fmaxf(v3, __shfl_xor_sync(0xffffffffu, v3, o));
    if (lane == 0) {
        gsc[warp] = __fadd_rn(m1, v2);
        if (detect_risk && (v2 - v3) < TAU) s_risky = 1;
    }
    __syncthreads();

    if (e == 0) {
        float bvals[TOPKG + 1];
#pragma unroll
        for (int g = 0; g < NGROUP; g++) gsel[g] = 0;
#pragma unroll
        for (int r = 0; r < TOPKG + 1; r++) {
            int bi = -1; float bv = -INFINITY;
#pragma unroll
            for (int g = 0; g < NGROUP; g++)
                if (!gsel[g] && gsc[g] > bv) { bv = gsc[g]; bi = g; }
            bvals[r] = bv;
            if (r < TOPKG) gsel[bi] = 1;
        }
        if (detect_risk && (bvals[TOPKG - 1] - bvals[TOPKG]) < 2.0f * TAU) s_risky = 1;
    }
    __syncthreads();

    float mv = gsel[warp] ? sb : 0.0f;
    keys[e] = ((unsigned long long)float_ord(mv) << 32) | (unsigned)(255 - e);
    __syncthreads();

#pragma unroll
    for (int r = 0; r < TOPK + 1; r++) {
        unsigned long long k = keys[e];
#pragma unroll
        for (int o = 16; o; o >>= 1) {
            unsigned long long k2 = __shfl_xor_sync(0xffffffffu, k, o);
            k = (k2 > k) ? k2 : k;
        }
        if (lane == 0) warpmax[warp] = k;
        __syncthreads();
        if (e == 0) {
            unsigned long long best = warpmax[0];
#pragma unroll
            for (int w = 1; w < NGROUP; w++) if (warpmax[w] > best) best = warpmax[w];
            int win = 255 - (int)(best & 0xFFu);
            sel[r]  = win;
            selv[r] = ord_to_float((unsigned)(best >> 32));
            keys[win] = 0ull;
        }
        __syncthreads();
    }

    if (e == 0) {
        if (detect_risk) {
#pragma unroll
            for (int r = 0; r < TOPK; r++)
                if ((selv[r] - selv[r + 1]) < TAU) s_risky = 1;
            if (s_risky) {
                int id = atomicAdd(&g_risk_count, 1);
                g_risk_ids[id] = t;
            }
        }
        float sum = 0.0f;
#pragma unroll
        for (int j = 0; j < TOPK; j++) sum = __fadd_rn(sum, sbs[sel[j]]);
#pragma unroll
        for (int j = 0; j < TOPK; j++) {
            out_w[(size_t)t * TOPK + j] = __fmul_rn(__fdiv_rn(sbs[sel[j]], sum), RSCALE);
            out_i[(size_t)t * TOPK + j] = (float)sel[j];
        }
    }
}

__global__ void gate_zero_kernel() { g_risk_count = 0; }

__global__ __launch_bounds__(256) void gate_routeA_kernel(
    const float* __restrict__ bias, float* __restrict__ out_w, float* __restrict__ out_i)
{
    const int t = blockIdx.x;
    const int e = threadIdx.x;
    float s = g_scores[(size_t)t * NEXP + e];
    float sg = 1.0f / (1.0f + __expf(-s));
    float sb = __fadd_rn(sg, bias[e]);
    route_token(sb, t, e, out_w, out_i, true);
}

// Pass B: near-exact rescoring via compensated fp32 Dot2 (err ~1e-13).
__global__ __launch_bounds__(256) void gate_routeB_kernel(
    const float* __restrict__ A, const float* __restrict__ B,
    const float* __restrict__ bias, float* __restrict__ out_w, float* __restrict__ out_i)
{
    const int cnt = g_risk_count;
    const int e = threadIdx.x;
    for (int i = blockIdx.x; i < cnt; i += gridDim.x) {
        const int t = g_risk_ids[i];
        const float4* a4 = reinterpret_cast<const float4*>(A + (size_t)t * DIMK);
        const float4* b4 = reinterpret_cast<const float4*>(B + (size_t)e * DIMK);
        float s = 0.0f, comp = 0.0f;
        for (int k = 0; k < DIMK / 4; k++) {
            float4 av = a4[k], bv = b4[k];
            float ax[4] = {av.x, av.y, av.z, av.w};
            float bx[4] = {bv.x, bv.y, bv.z, bv.w};
#pragma unroll
            for (int q = 0; q < 4; q++) {
                float p  = __fmul_rn(ax[q], bx[q]);
                float pe = fmaf(ax[q], bx[q], -p);          // exact product error
                float tS = __fadd_rn(s, p);
                float z  = __fsub_rn(tS, s);
                float se = __fadd_rn(__fsub_rn(s, __fsub_rn(tS, z)), __fsub_rn(p, z));
                s = tS;
                comp = __fadd_rn(comp, __fadd_rn(pe, se));
            }
        }
        double acc = (double)s + (double)comp;
        double sg64 = 1.0 / (1.0 + exp(-acc));
        float sb = __fadd_rn((float)sg64, bias[e]);
        __syncthreads();
        route_token(sb, t, e, out_w, out_i, false);
        __syncthreads();
    }
}

// ---------------------------------------------------------------------------
extern "C" void kernel_launch(void* const* d_in, const int* in_sizes, int n_in,
                              void* d_out, int out_size)
{
    const float* x = (const float*)d_in[0];
    const float* w = (const float*)d_in[1];
    const float* b = (const float*)d_in[2];
    float* out = (float*)d_out;
    float* out_w = out;
    float* out_i = out + (size_t)out_size / 2;

    const int smem_bytes = 2 * BUF_FLOATS * sizeof(float);
    cudaFuncSetAttribute(gemm_tc_kernel, cudaFuncAttributeMaxDynamicSharedMemorySize, smem_bytes);

    presplit_kernel<<<(NEXP * DIMK + 511) / 512, 512>>>(w);
    gate_zero_kernel<<<1, 1>>>();
    dim3 grid(NEXP / BN, M_TOK / BM);
    gemm_tc_kernel<<<grid, 256, smem_bytes>>>(x);
    gate_routeA_kernel<<<M_TOK, 256>>>(b, out_w, out_i);
    gate_routeB_kernel<<<1024, 256>>>(x, w, b, out_w, out_i);
}

// round 8
// speedup vs baseline: 2.9550x; 1.3112x over previous
#include <cuda_runtime.h>
#include <cuda_fp16.h>
#include <math.h>
#include <stdint.h>

#define M_TOK   16384
#define DIMK    7168
#define NEXP    256
#define NGROUP  8
#define TOPKG   4
#define TOPK    8
#define RSCALE  2.5f
#define TAU     8e-6f

#define NKT     (DIMK / 32)        // 224 k-tiles of 32
#define WFRAG_TOTAL (2 * NKT * 2048)   // [nblk2][kt224][2048 u32]

__device__ float    g_scores[(size_t)M_TOK * NEXP];
__device__ uint32_t g_wfh[WFRAG_TOTAL];   // W hi, fp16x2, fragment order
__device__ uint32_t g_wfm[WFRAG_TOTAL];   // W residual*2048, fp16x2, fragment order
__device__ int      g_risk_count;
__device__ int      g_risk_ids[M_TOK];

// ===================== helpers =====================
__device__ __forceinline__ uint32_t smem_u32(const void* p) {
    uint32_t a;
    asm("{ .reg .u64 t; cvta.to.shared.u64 t, %1; cvt.u32.u64 %0, t; }" : "=r"(a) : "l"(p));
    return a;
}
__device__ __forceinline__ void cp_async16(uint32_t dst, const void* src) {
    asm volatile("cp.async.cg.shared.global [%0], [%1], 16;" :: "r"(dst), "l"(src) : "memory");
}
__device__ __forceinline__ void cp_commit() {
    asm volatile("cp.async.commit_group;" ::: "memory");
}
template <int N> __device__ __forceinline__ void cp_wait() {
    asm volatile("cp.async.wait_group %0;" :: "n"(N) : "memory");
}
__device__ __forceinline__ void mma_f16(float* c, const uint32_t* a, uint32_t b0, uint32_t b1) {
    asm volatile(
        "mma.sync.aligned.m16n8k16.row.col.f32.f16.f16.f32 "
        "{%0,%1,%2,%3}, {%4,%5,%6,%7}, {%8,%9}, {%0,%1,%2,%3};"
        : "+f"(c[0]), "+f"(c[1]), "+f"(c[2]), "+f"(c[3])
        : "r"(a[0]), "r"(a[1]), "r"(a[2]), "r"(a[3]), "r"(b0), "r"(b1));
}
__device__ __forceinline__ uint32_t h2u(__half2 h) {
    uint32_t u; *reinterpret_cast<__half2*>(&u) = h; return u;
}
__device__ __forceinline__ void split_pair(float x0, float x1, uint32_t& hi, uint32_t& mi2) {
    __half2 hh = __floats2half2_rn(x0, x1);
    float f0 = __low2float(hh), f1 = __high2float(hh);
    __half2 mm = __floats2half2_rn((x0 - f0) * 2048.0f, (x1 - f1) * 2048.0f);
    hi = h2u(hh); mi2 = h2u(mm);
}

// ===================== presplit: W -> fragment-order fp16x2 =====================
// layout per (nblk,kt): 2048 u32 = [wn1(2)][s(2)][lane(32)][slot(16)]
// slot is bank-swizzled: logical chunk cc (= reg*2 + (ni>>2)) lives at slot group cc^((lane>>1)&3)
__global__ __launch_bounds__(256) void presplit_kernel(const float* __restrict__ W) {
    int gid = blockIdx.x * 256 + threadIdx.x;
    if (gid >= WFRAG_TOTAL) return;
    int blk  = gid >> 11;           // (nblk*NKT + kt)
    int kt   = blk % NKT;
    int nblk = blk / NKT;
    int ws   = gid & 2047;
    int wn1  = ws >> 10;
    int s    = (ws >> 9) & 1;
    int lane = (ws >> 4) & 31;
    int slot = ws & 15;
    int cc   = (slot >> 2) ^ ((lane >> 1) & 3);
    int L    = cc * 4 + (slot & 3);
    int reg  = L >> 3;
    int ni   = L & 7;
    int n  = nblk * 128 + wn1 * 64 + ni * 8 + (lane >> 2);
    int k0 = kt * 32 + s * 16 + 2 * (lane & 3) + (reg ? 8 : 0);
    float w0 = W[(size_t)n * DIMK + k0];
    float w1 = W[(size_t)n * DIMK + k0 + 1];
    uint32_t hi, mi2;
    split_pair(w0, w1, hi, mi2);
    g_wfh[gid] = hi;
    g_wfm[gid] = mi2;
}

// ===================== fp16x3 tensor GEMM =====================
// CTA 128x128, 256 thr = 8 warps (4M x 2N), warp tile 32x64 (mi2 x ni8), BK=32 (2 k16 steps).
// smem/buffer: A 16KB (row 128B, chunk-xor swizzle) + Bh 8KB + Bm 8KB = 32KB, double buffered.
#define BUFB 32768

__global__ __launch_bounds__(256, 1) void gemm_tc_kernel(const float* __restrict__ X) {
    extern __shared__ char smch[];
    const int tid  = threadIdx.x;
    const int lane = tid & 31;
    const int wid  = tid >> 5;
    const int m0   = blockIdx.y * 128;
    const int nblk = blockIdx.x;
    const int wm_  = (wid >> 1) * 32;
    const int wn1  = wid & 1;
    const int q    = lane >> 2;
    const int c    = lane & 3;
    const int sw2  = (lane >> 1) & 3;

    float accH[2][8][4], accS[2][8][4];
#pragma unroll
    for (int mi = 0; mi < 2; mi++)
#pragma unroll
        for (int ni = 0; ni < 8; ni++)
#pragma unroll
            for (int z = 0; z < 4; z++) { accH[mi][ni][z] = 0.0f; accS[mi][ni][z] = 0.0f; }

    const uint32_t sb = smem_u32(smch);
    const int arow = tid >> 3;          // 0..31
    const int achk = tid & 7;           // chunk 0..7

    auto load_tiles = [&](int t, int buf) {
        const uint32_t ab = sb + buf * BUFB;
        // A: 128 rows x 32 floats, chunk-xor swizzle
#pragma unroll
        for (int j = 0; j < 4; j++) {
            int row = arow + j * 32;
            cp_async16(ab + row * 128 + ((achk ^ (row & 7)) * 16),
                       X + (size_t)(m0 + row) * DIMK + t * 32 + achk * 4);
        }
        // B: fragment-order contiguous (2048 u32 each)
        const uint32_t bsrc = (uint32_t)((nblk * NKT + t) * 2048);
#pragma unroll
        for (int j = 0; j < 2; j++) {
            cp_async16(ab + 16384 + tid * 32 + j * 16, g_wfh + bsrc + tid * 8 + j * 4);
            cp_async16(ab + 24576 + tid * 32 + j * 16, g_wfm + bsrc + tid * 8 + j * 4);
        }
    };

    load_tiles(0, 0);
    cp_commit();

    for (int t = 0; t < NKT; t++) {
        const int buf = t & 1;
        if (t + 1 < NKT) {
            load_tiles(t + 1, buf ^ 1);
            cp_commit();
            cp_wait<1>();
        } else {
            cp_wait<0>();
        }
        __syncthreads();

        const char* bufp = smch + buf * BUFB;

#pragma unroll
        for (int s = 0; s < 2; s++) {
            // ---- B fragments: 8 conflict-free LDS.128 ----
            uint32_t bh[2][8], bm[2][8];
            const char* bp = bufp + 16384 + ((wn1 * 2 + s) * 512 + lane * 16) * 4;
#pragma unroll
            for (int cc = 0; cc < 4; cc++) {
                uint4 vh = *reinterpret_cast<const uint4*>(bp + ((cc ^ sw2) * 16));
                uint4 vm = *reinterpret_cast<const uint4*>(bp + 8192 + ((cc ^ sw2) * 16));
                int rg = cc >> 1, hf = (cc & 1) * 4;
                bh[rg][hf + 0] = vh.x; bh[rg][hf + 1] = vh.y; bh[rg][hf + 2] = vh.z; bh[rg][hf + 3] = vh.w;
                bm[rg][hf + 0] = vm.x; bm[rg][hf + 1] = vm.y; bm[rg][hf + 2] = vm.z; bm[rg][hf + 3] = vm.w;
            }
            // ---- A fragments: 8 conflict-free LDS.64 + in-register split ----
            uint32_t ah[2][4], am[2][4];
#pragma unroll
            for (int mi = 0; mi < 2; mi++) {
                int r  = wm_ + mi * 16 + q;
                int ck0 = (s * 4 + (c >> 1)) ^ q;      // chunk for k-pair
                int ck1 = (s * 4 + (c >> 1) + 2) ^ q;  // chunk for k+8 pair
                int woff = 2 * (c & 1) * 4;
                float2 p00 = *reinterpret_cast<const float2*>(bufp + r * 128 + ck0 * 16 + woff);
                float2 p10 = *reinterpret_cast<const float2*>(bufp + (r + 8) * 128 + ck0 * 16 + woff);
                float2 p01 = *reinterpret_cast<const float2*>(bufp + r * 128 + ck1 * 16 + woff);
                float2 p11 = *reinterpret_cast<const float2*>(bufp + (r + 8) * 128 + ck1 * 16 + woff);
                split_pair(p00.x, p00.y, ah[mi][0], am[mi][0]);
                split_pair(p10.x, p10.y, ah[mi][1], am[mi][1]);
                split_pair(p01.x, p01.y, ah[mi][2], am[mi][2]);
                split_pair(p11.x, p11.y, ah[mi][3], am[mi][3]);
            }
            // ---- 48 MMAs ----
#pragma unroll
            for (int mi = 0; mi < 2; mi++)
#pragma unroll
                for (int ni = 0; ni < 8; ni++) {
                    mma_f16(accH[mi][ni], ah[mi], bh[0][ni], bh[1][ni]);
                    mma_f16(accS[mi][ni], ah[mi], bm[0][ni], bm[1][ni]);
                    mma_f16(accS[mi][ni], am[mi], bh[0][ni], bh[1][ni]);
                }
        }
        __syncthreads();
    }

    const float inv2048 = 1.0f / 2048.0f;
#pragma unroll
    for (int mi = 0; mi < 2; mi++)
#pragma unroll
        for (int ni = 0; ni < 8; ni++) {
            int row = m0 + wm_ + mi * 16 + q;
            int col = nblk * 128 + wn1 * 64 + ni * 8 + c * 2;
            *reinterpret_cast<float2*>(&g_scores[(size_t)row * NEXP + col]) =
                make_float2(fmaf(accS[mi][ni][0], inv2048, accH[mi][ni][0]),
                            fmaf(accS[mi][ni][1], inv2048, accH[mi][ni][1]));
            *reinterpret_cast<float2*>(&g_scores[(size_t)(row + 8) * NEXP + col]) =
                make_float2(fmaf(accS[mi][ni][2], inv2048, accH[mi][ni][2]),
                            fmaf(accS[mi][ni][3], inv2048, accH[mi][ni][3]));
        }
}

// ===================== routing (two-pass, proven) =====================
__device__ __forceinline__ unsigned float_ord(float f) {
    unsigned u = __float_as_uint(f);
    return (u & 0x80000000u) ? ~u : (u | 0x80000000u);
}
__device__ __forceinline__ float ord_to_float(unsigned o) {
    unsigned u = (o & 0x80000000u) ? (o ^ 0x80000000u) : ~o;
    return __uint_as_float(u);
}

__device__ __forceinline__ void route_token(float sbv, int t, int e,
                                            float* out_w, float* out_i, bool detect_risk)
{
    const int warp = e >> 5, lane = e & 31;
    __shared__ float sbs[NEXP];
    __shared__ unsigned long long keys[NEXP];
    __shared__ float gsc[NGROUP];
    __shared__ int   gsel[NGROUP];
    __shared__ unsigned long long warpmax[NGROUP];
    __shared__ int   sel[TOPK + 1];
    __shared__ float selv[TOPK + 1];
    __shared__ int   s_risky;

    if (e == 0) s_risky = 0;
    sbs[e] = sbv;

    float m1 = sbv;
#pragma unroll
    for (int o = 16; o; o >>= 1) m1 = fmaxf(m1, __shfl_xor_sync(0xffffffffu, m1, o));
    unsigned bal1 = __ballot_sync(0xffffffffu, sbv == m1);
    int arg1 = __ffs(bal1) - 1;
    float x2 = (lane == arg1) ? -INFINITY : sbv;
    float v2 = x2;
#pragma unroll
    for (int o = 16; o; o >>= 1) v2 = fmaxf(v2, __shfl_xor_sync(0xffffffffu, v2, o));
    unsigned bal2 = __ballot_sync(0xffffffffu, x2 == v2);
    int arg2 = __ffs(bal2) - 1;
    float x3 = (lane == arg1 || lane == arg2) ? -INFINITY : sbv;
    float v3 = x3;
#pragma unroll
    for (int o = 16; o; o >>= 1) v3 = fmaxf(v3, __shfl_xor_sync(0xffffffffu, v3, o));
    if (lane == 0) {
        gsc[warp] = __fadd_rn(m1, v2);
        if (detect_risk && (v2 - v3) < TAU) s_risky = 1;
    }
    __syncthreads();

    if (e == 0) {
        float bvals[TOPKG + 1];
#pragma unroll
        for (int g = 0; g < NGROUP; g++) gsel[g] = 0;
#pragma unroll
        for (int r = 0; r < TOPKG + 1; r++) {
            int bi = -1; float bv = -INFINITY;
#pragma unroll
            for (int g = 0; g < NGROUP; g++)
                if (!gsel[g] && gsc[g] > bv) { bv = gsc[g]; bi = g; }
            bvals[r] = bv;
            if (r < TOPKG) gsel[bi] = 1;
        }
        if (detect_risk && (bvals[TOPKG - 1] - bvals[TOPKG]) < 2.0f * TAU) s_risky = 1;
    }
    __syncthreads();

    float mv = gsel[warp] ? sbv : 0.0f;
    keys[e] = ((unsigned long long)float_ord(mv) << 32) | (unsigned)(255 - e);
    __syncthreads();

#pragma unroll
    for (int r = 0; r < TOPK + 1; r++) {
        unsigned long long k = keys[e];
#pragma unroll
        for (int o = 16; o; o >>= 1) {
            unsigned long long k2 = __shfl_xor_sync(0xffffffffu, k, o);
            k = (k2 > k) ? k2 : k;
        }
        if (lane == 0) warpmax[warp] = k;
        __syncthreads();
        if (e == 0) {
            unsigned long long best = warpmax[0];
#pragma unroll
            for (int w = 1; w < NGROUP; w++) if (warpmax[w] > best) best = warpmax[w];
            int win = 255 - (int)(best & 0xFFu);
            sel[r]  = win;
            selv[r] = ord_to_float((unsigned)(best >> 32));
            keys[win] = 0ull;
        }
        __syncthreads();
    }

    if (e == 0) {
        if (detect_risk) {
#pragma unroll
            for (int r = 0; r < TOPK; r++)
                if ((selv[r] - selv[r + 1]) < TAU) s_risky = 1;
            if (s_risky) {
                int id = atomicAdd(&g_risk_count, 1);
                g_risk_ids[id] = t;
            }
        }
        float sum = 0.0f;
#pragma unroll
        for (int j = 0; j < TOPK; j++) sum = __fadd_rn(sum, sbs[sel[j]]);
#pragma unroll
        for (int j = 0; j < TOPK; j++) {
            out_w[(size_t)t * TOPK + j] = __fmul_rn(__fdiv_rn(sbs[sel[j]], sum), RSCALE);
            out_i[(size_t)t * TOPK + j] = (float)sel[j];
        }
    }
}

__global__ void gate_zero_kernel() { g_risk_count = 0; }

__global__ __launch_bounds__(256) void gate_routeA_kernel(
    const float* __restrict__ bias, float* __restrict__ out_w, float* __restrict__ out_i)
{
    const int t = blockIdx.x;
    const int e = threadIdx.x;
    float s = g_scores[(size_t)t * NEXP + e];
    float sg = 1.0f / (1.0f + __expf(-s));
    float sbv = __fadd_rn(sg, bias[e]);
    route_token(sbv, t, e, out_w, out_i, true);
}

__global__ __launch_bounds__(256) void gate_routeB_kernel(
    const float* __restrict__ A, const float* __restrict__ B,
    const float* __restrict__ bias, float* __restrict__ out_w, float* __restrict__ out_i)
{
    const int cnt = g_risk_count;
    const int e = threadIdx.x;
    for (int i = blockIdx.x; i < cnt; i += gridDim.x) {
        const int t = g_risk_ids[i];
        const float4* a4 = reinterpret_cast<const float4*>(A + (size_t)t * DIMK);
        const float4* b4 = reinterpret_cast<const float4*>(B + (size_t)e * DIMK);
        float s = 0.0f, comp = 0.0f;
        for (int k = 0; k < DIMK / 4; k++) {
            float4 av = a4[k], bv = b4[k];
            float ax[4] = {av.x, av.y, av.z, av.w};
            float bx[4] = {bv.x, bv.y, bv.z, bv.w};
#pragma unroll
            for (int z = 0; z < 4; z++) {
                float p  = __fmul_rn(ax[z], bx[z]);
                float pe = fmaf(ax[z], bx[z], -p);
                float tS = __fadd_rn(s, p);
                float zz = __fsub_rn(tS, s);
                float se = __fadd_rn(__fsub_rn(s, __fsub_rn(tS, zz)), __fsub_rn(p, zz));
                s = tS;
                comp = __fadd_rn(comp, __fadd_rn(pe, se));
            }
        }
        double acc = (double)s + (double)comp;
        double sg64 = 1.0 / (1.0 + exp(-acc));
        float sbv = __fadd_rn((float)sg64, bias[e]);
        __syncthreads();
        route_token(sbv, t, e, out_w, out_i, false);
        __syncthreads();
    }
}

// ---------------------------------------------------------------------------
extern "C" void kernel_launch(void* const* d_in, const int* in_sizes, int n_in,
                              void* d_out, int out_size)
{
    const float* x = (const float*)d_in[0];
    const float* w = (const float*)d_in[1];
    const float* b = (const float*)d_in[2];
    float* out = (float*)d_out;
    float* out_w = out;
    float* out_i = out + (size_t)out_size / 2;

    cudaFuncSetAttribute(gemm_tc_kernel, cudaFuncAttributeMaxDynamicSharedMemorySize, 2 * BUFB);

    presplit_kernel<<<(WFRAG_TOTAL + 255) / 256, 256>>>(w);
    gate_zero_kernel<<<1, 1>>>();
    dim3 grid(2, 128);
    gemm_tc_kernel<<<grid, 256, 2 * BUFB>>>(x);
    gate_routeA_kernel<<<M_TOK, 256>>>(b, out_w, out_i);
    gate_routeB_kernel<<<1024, 256>>>(x, w, b, out_w, out_i);
}